// round 3
// baseline (speedup 1.0000x reference)
#include <cuda_runtime.h>

// Triline interpolation:
//   out[b, :] = lerp(x_line, cx) + lerp(y_line, cy) + lerp(z_line, cz)
// B = 1M points, C = 64 channels, N = 512 rows per line.
//
// Layout: 16 threads per point; each thread handles 4 channels (one float4).
// Output stores fully coalesced; table-row gathers are 256B contiguous per
// point (16 lanes x float4) and L2-resident (3 tables = 384 KB total).

#define C_CH   64
#define N_ROWS 512

__global__ __launch_bounds__(256) void triline_kernel(
    const float* __restrict__ coords,   // [B, 3]
    const float* __restrict__ x_line,   // [N, C]
    const float* __restrict__ y_line,   // [N, C]
    const float* __restrict__ z_line,   // [N, C]
    const float* __restrict__ grid,     // [N]
    float* __restrict__ out,            // [B, C]
    int B)
{
    const int tid = blockIdx.x * blockDim.x + threadIdx.x;
    const int b   = tid >> 4;            // point index
    const int cg  = (tid & 15) << 2;     // channel offset (float4 granularity)
    if (b >= B) return;

    const float g0    = __ldg(grid);
    const float invdx = 1.0f / (__ldg(grid + 1) - g0);

    // Load the 3 coordinates for this point.
    const float cx = __ldg(coords + 3 * b + 0);
    const float cy = __ldg(coords + 3 * b + 1);
    const float cz = __ldg(coords + 3 * b + 2);

    // Fractional positions and clamped base indices.
    float px = (cx - g0) * invdx;
    float py = (cy - g0) * invdx;
    float pz = (cz - g0) * invdx;

    int ix = (int)floorf(px); ix = min(max(ix, 0), N_ROWS - 2);
    int iy = (int)floorf(py); iy = min(max(iy, 0), N_ROWS - 2);
    int iz = (int)floorf(pz); iz = min(max(iz, 0), N_ROWS - 2);

    const float wx = px - (float)ix;
    const float wy = py - (float)iy;
    const float wz = pz - (float)iz;

    // Issue all 6 gathers up front for maximum MLP.
    const float4* xr = (const float4*)(x_line + ix * C_CH + cg);
    const float4* yr = (const float4*)(y_line + iy * C_CH + cg);
    const float4* zr = (const float4*)(z_line + iz * C_CH + cg);

    const float4 x0 = __ldg(xr);
    const float4 x1 = __ldg(xr + (C_CH / 4));
    const float4 y0 = __ldg(yr);
    const float4 y1 = __ldg(yr + (C_CH / 4));
    const float4 z0 = __ldg(zr);
    const float4 z1 = __ldg(zr + (C_CH / 4));

    float4 r;
    r.x = fmaf(wx, x1.x - x0.x, x0.x) + fmaf(wy, y1.x - y0.x, y0.x) + fmaf(wz, z1.x - z0.x, z0.x);
    r.y = fmaf(wx, x1.y - x0.y, x0.y) + fmaf(wy, y1.y - y0.y, y0.y) + fmaf(wz, z1.y - z0.y, z0.y);
    r.z = fmaf(wx, x1.z - x0.z, x0.z) + fmaf(wy, y1.z - y0.z, y0.z) + fmaf(wz, z1.z - z0.z, z0.z);
    r.w = fmaf(wx, x1.w - x0.w, x0.w) + fmaf(wy, y1.w - y0.w, y0.w) + fmaf(wz, z1.w - z0.w, z0.w);

    *(float4*)(out + (size_t)b * C_CH + cg) = r;
}

extern "C" void kernel_launch(void* const* d_in, const int* in_sizes, int n_in,
                              void* d_out, int out_size)
{
    const float* coords = (const float*)d_in[0];
    const float* x_line = (const float*)d_in[1];
    const float* y_line = (const float*)d_in[2];
    const float* z_line = (const float*)d_in[3];
    const float* grid   = (const float*)d_in[4];
    float* out = (float*)d_out;

    const int B = in_sizes[0] / 3;          // 1048576
    const int total_threads = B * 16;       // 16 threads per point
    const int block = 256;
    const int nblocks = (total_threads + block - 1) / block;

    triline_kernel<<<nblocks, block>>>(coords, x_line, y_line, z_line, grid, out, B);
}